// round 16
// baseline (speedup 1.0000x reference)
#include <cuda_runtime.h>
#include <math.h>

// Shapes fixed by the reference:
//  B=16,T=32 -> BT=512 ; NP=8, NG=4, J=14, H=256
#define BT      512
#define HEAT_N  (512 * 256 * 256)    // 33,554,432 floats
#define N4      (HEAT_N / 4)         // 8,388,608 float4
#define NIT     (N4 / 32)            // 262,144 warp-iterations (512B each)
#define NBLK    1024
#define NHW     7680                 // heat warps: 512*7 + 512*8

#define INV_HEAT (1.0f / (float)HEAT_N)
#define INV_BT   (1.0f / 512.0f)
#define INV_POSE (1.0f / (512.0f * 8.0f * 14.0f))

// Staging buffer layout (floats): pp 336 | gp 168 | pc 16 | gc 8 | sc 8 |
//                                 po 16 | go 8 | ps 32 | gs 16  = 608 floats
#define PF_PP 0
#define PF_GP 336
#define PF_PC 504
#define PF_GC 520
#define PF_SC 528
#define PF_PO 536
#define PF_GO 552
#define PF_PS 560
#define PF_GS 592
#define PF_FLOATS 608
#define PF_CHUNKS 152               // 608 floats = 152 x float4

__device__ float        g_heat_part[NBLK];
__device__ float        g_match[BT];
__device__ unsigned int g_count;     // ticket counter (self-resetting)

// Monotone float->uint map: equal floats -> equal keys, order preserved.
__device__ __forceinline__ unsigned f2ord(float v) {
    unsigned u = __float_as_uint(v);
    return (u & 0x80000000u) ? ~u : (u | 0x80000000u);
}

__device__ __forceinline__ unsigned long long umin64(unsigned long long a,
                                                     unsigned long long b) {
    return a < b ? a : b;
}

// Lexicographic rank -> k-permutation of range(8), k=4 (itertools order).
__device__ __forceinline__ void decode_perm(int r, int* p) {
    const int divs[4] = {210, 30, 5, 1};
    unsigned mask = 0xFFu;
#pragma unroll
    for (int k = 0; k < 4; k++) {
        int d = r / divs[k];
        r -= d * divs[k];
        unsigned m = mask;
#pragma unroll
        for (int q = 0; q < 7; q++)
            if (q < d) m &= (m - 1);
        int idx = __ffs(m) - 1;
        mask &= ~(1u << idx);
        p[k] = idx;
    }
}

// ---------------------------------------------------------------------------
// Fused kernel: 1024 blocks x 256 threads (8-warp schedule shape).
//   Blocks 0..511 : warps 0-6 heat, warp 7 = one match cell (hidden).
//   Blocks 512+   : warps 0-7 heat.
//   Heat warps iterate STRIDED (it += NHW): uniform address sampling ->
//   L2-die latency averages out -> minimal finish spread.
//   h-mapping puts the NIT%NHW=1024 extra iterations on PURE-heat blocks
//   (512+), keeping match blocks at the lighter 34-iteration share.
//   Last block to finish combines all partials (L2-hot) and writes out[0].
// ---------------------------------------------------------------------------
__global__ void __launch_bounds__(256, 7)
k_fused(const float4* __restrict__ ha,   // hor_heatmap as float4
        const float4* __restrict__ hb,   // gt_heatmap  as float4
        const float* __restrict__ po_all,   // hor_offset  (BT,8,2)
        const float* __restrict__ ps_all,   // hor_bsize   (BT,8,4)
        const float* __restrict__ pc_all,   // hor_center  (BT,8,2)
        const float* __restrict__ sc_all,   // scores      (BT,8)
        const float* __restrict__ pp_all,   // x_pose3d    (BT,8,14,3)
        const float* __restrict__ gs_all,   // gt_boxes_wh (BT,4,4)
        const float* __restrict__ go_all,   // gt_offset   (BT,4,2)
        const float* __restrict__ gc_all,   // gt_center   (BT,4,2)
        const float* __restrict__ gp_all,   // gt_pose3d   (BT,4,14,3)
        float* __restrict__ out)
{
    const int bid  = blockIdx.x;
    const int t    = threadIdx.x;
    const int w    = t >> 5;
    const int lane = t & 31;

    __shared__ float sred[256];
    __shared__ float swp[8];               // per-warp partials
    __shared__ float s_pref[PF_FLOATS];
    __shared__ float sC[64];               // [Cb 32 | Cp 32] for the match warp
    __shared__ bool  isLast;

    const bool isMatch = (bid < BT) && (w == 7);

    if (!isMatch) {
        // ------------- Heat warps: strided warp-iterations ----------------
        // Pure-heat blocks own h in [0,4096) -> they absorb the remainder.
        int h = (bid < BT) ? (4096 + bid * 7 + w)
                           : ((bid - BT) * 8 + w);

        float acc = 0.f;
        for (int it = h; it < NIT; it += NHW) {
            int i = it * 32 + lane;
            float4 x = ha[i];
            float4 y = hb[i];
            float dx = x.x - y.x, dy = x.y - y.y, dz = x.z - y.z, dw = x.w - y.w;
            acc += dx * dx + dy * dy + dz * dz + dw * dw;
        }
#pragma unroll
        for (int o = 16; o > 0; o >>= 1)
            acc += __shfl_down_sync(0xffffffffu, acc, o);
        if (lane == 0) swp[w] = acc;
    } else {
        // ---------------- Match warp (warp 7 of blocks 0..511) ------------
        const int bt = bid;

        // Stage the whole 2.4KB working set as float4 (coalesced, 5/lane).
        for (int c = lane; c < PF_CHUNKS; c += 32) {
            const float* src;
            if      (c <  84) src = pp_all + bt * 336 + c * 4;
            else if (c < 126) src = gp_all + bt * 168 + (c -  84) * 4;
            else if (c < 130) src = pc_all + bt * 16  + (c - 126) * 4;
            else if (c < 132) src = gc_all + bt * 8   + (c - 130) * 4;
            else if (c < 134) src = sc_all + bt * 8   + (c - 132) * 4;
            else if (c < 138) src = po_all + bt * 16  + (c - 134) * 4;
            else if (c < 140) src = go_all + bt * 8   + (c - 138) * 4;
            else if (c < 148) src = ps_all + bt * 32  + (c - 140) * 4;
            else              src = gs_all + bt * 16  + (c - 148) * 4;
            float4 v = *(const float4*)src;
            *(float4*)(s_pref + c * 4) = v;
        }
        __syncwarp();

        const float* s_pp = s_pref + PF_PP;
        const float* s_gp = s_pref + PF_GP;

        // Cost entries: lane = i*4+j covers all 32 (i,j) pairs, from shared.
        const int i = lane >> 2, j = lane & 3;
        {
            float dx = s_pref[PF_PC + 2 * i]     - s_pref[PF_GC + 2 * j];
            float dy = s_pref[PF_PC + 2 * i + 1] - s_pref[PF_GC + 2 * j + 1];
            sC[lane] = sqrtf(dx * dx + dy * dy) - s_pref[PF_SC + i];

            const float* pi = s_pp + i * 42;
            const float* gj = s_gp + j * 42;
            float s = 0.f;
#pragma unroll
            for (int k = 0; k < 42; k++) {
                float d = pi[k] - gj[k];
                s += d * d;
            }
            sC[32 + lane] = sqrtf(s);
        }
        __syncwarp();

        // Sweep all 1680 combos: 56 (d0,d1)-prefixes x 30 each.
        // rank = ((d0*7+d1)*6+d2)*5+d3 (itertools lexicographic order);
        // min over (orderedFloat<<32 | rank) = exact first-argmin.
        unsigned long long kb = ~0ull, kp = ~0ull;
        for (int p = lane; p < 56; p += 32) {
            int d0 = p / 7, d1 = p - d0 * 7;
            int i0 = d0;
            int i1 = d1 + (d1 >= d0);
            int a1 = min(i0, i1), b1 = max(i0, i1);
            float sb01 = sC[i0 * 4 + 0] + sC[i1 * 4 + 1];
            float sp01 = sC[32 + i0 * 4 + 0] + sC[32 + i1 * 4 + 1];
            int rbase = p * 30;
#pragma unroll
            for (int d2 = 0; d2 < 6; d2++) {
                int i2 = d2;
                i2 += (i2 >= a1);
                i2 += (i2 >= b1);
                float sb2 = sb01 + sC[i2 * 4 + 2];
                float sp2 = sp01 + sC[32 + i2 * 4 + 2];
                int a2, b2, c2;
                if (i2 < a1)      { a2 = i2; b2 = a1; c2 = b1; }
                else if (i2 < b1) { a2 = a1; b2 = i2; c2 = b1; }
                else              { a2 = a1; b2 = b1; c2 = i2; }
#pragma unroll
                for (int d3 = 0; d3 < 5; d3++) {
                    int i3 = d3;
                    i3 += (i3 >= a2);
                    i3 += (i3 >= b2);
                    i3 += (i3 >= c2);
                    float tb = sb2 + sC[i3 * 4 + 3];
                    float tp = sp2 + sC[32 + i3 * 4 + 3];
                    unsigned r = (unsigned)(rbase + d2 * 5 + d3);
                    kb = umin64(kb, ((unsigned long long)f2ord(tb) << 32) | r);
                    kp = umin64(kp, ((unsigned long long)f2ord(tp) << 32) | r);
                }
            }
        }
#pragma unroll
        for (int o = 16; o > 0; o >>= 1) {
            kb = umin64(kb, __shfl_xor_sync(0xffffffffu, kb, o));
            kp = umin64(kp, __shfl_xor_sync(0xffffffffu, kp, o));
        }

        int pb[4], pq[4];
        decode_perm((int)(kb & 0xFFFFFFFFu), pb);
        decode_perm((int)(kp & 0xFFFFFFFFu), pq);

        // Tail losses: lane-parallel, all from shared, fixed-order sum.
        float pose_acc = 0.f, box_acc = 0.f;
        for (int idx = lane; idx < 168; idx += 32) {
            int jj = idx / 42, k = idx - jj * 42;
            float d = s_pp[pq[jj] * 42 + k] - s_gp[idx];
            pose_acc += d * d;
        }
        if (lane < 24) {
            int jj = lane / 6, ww = lane - jj * 6;
            int ii = pb[jj];
            if (ww < 2) {
                box_acc = 0.5f * fabsf(s_pref[PF_PO + ii * 2 + ww] -
                                       s_pref[PF_GO + jj * 2 + ww]);
            } else {
                int k = ww - 2;
                box_acc = 0.25f * fabsf(s_pref[PF_PS + ii * 4 + k] -
                                        s_pref[PF_GS + jj * 4 + k]);
            }
        }
        float v = pose_acc * INV_POSE + box_acc * INV_BT;
#pragma unroll
        for (int o = 16; o > 0; o >>= 1)
            v += __shfl_down_sync(0xffffffffu, v, o);
        if (lane == 0) {
            g_match[bt] = v;
            swp[7] = 0.f;            // match warp's heat contribution
        }
    }

    // ---------------- Block reduction over 8 warp partials ----------------
    __syncthreads();
    if (t == 0) {
        float s = ((swp[0] + swp[1]) + (swp[2] + swp[3])) +
                  ((swp[4] + swp[5]) + (swp[6] + swp[7]));
        g_heat_part[bid] = s;
    }

    // ---------------- Last-block ticket combine (threadFenceReduction) ----
    if (t == 0) {
        __threadfence();
        unsigned old = atomicAdd(&g_count, 1u);
        isLast = (old == NBLK - 1);
    }
    __syncthreads();

    if (isLast) {
        __threadfence();
        float v = g_heat_part[t] + g_heat_part[t + 256] +
                  g_heat_part[t + 512] + g_heat_part[t + 768];
        v *= INV_HEAT;
        v += g_match[t] + g_match[t + 256];
        sred[t] = v;
        __syncthreads();
#pragma unroll
        for (int o = 128; o > 0; o >>= 1) {
            if (t < o) sred[t] += sred[t + o];
            __syncthreads();
        }
        if (t == 0) {
            out[0]  = sred[0];
            g_count = 0;             // reset for next graph replay
        }
    }
}

// ---------------------------------------------------------------------------
extern "C" void kernel_launch(void* const* d_in, const int* in_sizes, int n_in,
                              void* d_out, int out_size) {
    const float* hor_heatmap = (const float*)d_in[0];
    const float* hor_offset  = (const float*)d_in[1];
    const float* hor_bsize   = (const float*)d_in[2];
    const float* hor_center  = (const float*)d_in[3];
    const float* scores      = (const float*)d_in[4];
    const float* x_pose3d    = (const float*)d_in[5];
    const float* gt_heatmap  = (const float*)d_in[6];
    const float* gt_boxes_wh = (const float*)d_in[7];
    const float* gt_offset   = (const float*)d_in[8];
    const float* gt_center   = (const float*)d_in[9];
    const float* gt_pose3d   = (const float*)d_in[10];

    k_fused<<<NBLK, 256>>>((const float4*)hor_heatmap, (const float4*)gt_heatmap,
                           hor_offset, hor_bsize, hor_center, scores, x_pose3d,
                           gt_boxes_wh, gt_offset, gt_center, gt_pose3d,
                           (float*)d_out);
}

// round 17
// speedup vs baseline: 1.0028x; 1.0028x over previous
#include <cuda_runtime.h>
#include <math.h>

// Shapes fixed by the reference:
//  B=16,T=32 -> BT=512 ; NP=8, NG=4, J=14, H=256
#define BT      512
#define HEAT_N  (512 * 256 * 256)    // 33,554,432 floats
#define N4      (HEAT_N / 4)         // 8,388,608 float4
#define NIT     (N4 / 32)            // 262,144 warp-iterations (512B each)
#define NBLK    1024
#define NHW     7680                 // heat warps: 512*7 + 512*8

#define INV_HEAT (1.0f / (float)HEAT_N)
#define INV_BT   (1.0f / 512.0f)
#define INV_POSE (1.0f / (512.0f * 8.0f * 14.0f))

// Staging buffer layout (floats): pp 336 | gp 168 | pc 16 | gc 8 | sc 8 |
//                                 po 16 | go 8 | ps 32 | gs 16  = 608 floats
#define PF_PP 0
#define PF_GP 336
#define PF_PC 504
#define PF_GC 520
#define PF_SC 528
#define PF_PO 536
#define PF_GO 552
#define PF_PS 560
#define PF_GS 592
#define PF_FLOATS 608
#define PF_CHUNKS 152               // 608 floats = 152 x float4

__device__ float        g_heat_part[NBLK];
__device__ float        g_match[BT];
__device__ unsigned int g_count;     // ticket counter (self-resetting)

// Monotone float->uint map: equal floats -> equal keys, order preserved.
__device__ __forceinline__ unsigned f2ord(float v) {
    unsigned u = __float_as_uint(v);
    return (u & 0x80000000u) ? ~u : (u | 0x80000000u);
}

__device__ __forceinline__ unsigned long long umin64(unsigned long long a,
                                                     unsigned long long b) {
    return a < b ? a : b;
}

// Lexicographic rank -> k-permutation of range(8), k=4 (itertools order).
__device__ __forceinline__ void decode_perm(int r, int* p) {
    const int divs[4] = {210, 30, 5, 1};
    unsigned mask = 0xFFu;
#pragma unroll
    for (int k = 0; k < 4; k++) {
        int d = r / divs[k];
        r -= d * divs[k];
        unsigned m = mask;
#pragma unroll
        for (int q = 0; q < 7; q++)
            if (q < d) m &= (m - 1);
        int idx = __ffs(m) - 1;
        mask &= ~(1u << idx);
        p[k] = idx;
    }
}

// ---------------------------------------------------------------------------
// Fused kernel: 1024 blocks x 256 threads (8-warp R1 schedule shape).
//   Blocks 0..511 : warps 0-6 heat, warp 7 = one match cell (hidden).
//   Blocks 512+   : warps 0-7 heat.
//   Heat warps iterate STRIDED (it += NHW): uniform sampling of the address
//   space -> per-warp L2-die latency averages out -> minimal finish spread.
//   Last block to finish combines all partials (L2-hot) and writes out[0].
//   (R15 configuration — measured 43.2us @ 6321 GB/s, DRAM 79.8%.)
// ---------------------------------------------------------------------------
__global__ void __launch_bounds__(256, 7)
k_fused(const float4* __restrict__ ha,   // hor_heatmap as float4
        const float4* __restrict__ hb,   // gt_heatmap  as float4
        const float* __restrict__ po_all,   // hor_offset  (BT,8,2)
        const float* __restrict__ ps_all,   // hor_bsize   (BT,8,4)
        const float* __restrict__ pc_all,   // hor_center  (BT,8,2)
        const float* __restrict__ sc_all,   // scores      (BT,8)
        const float* __restrict__ pp_all,   // x_pose3d    (BT,8,14,3)
        const float* __restrict__ gs_all,   // gt_boxes_wh (BT,4,4)
        const float* __restrict__ go_all,   // gt_offset   (BT,4,2)
        const float* __restrict__ gc_all,   // gt_center   (BT,4,2)
        const float* __restrict__ gp_all,   // gt_pose3d   (BT,4,14,3)
        float* __restrict__ out)
{
    const int bid  = blockIdx.x;
    const int t    = threadIdx.x;
    const int w    = t >> 5;
    const int lane = t & 31;

    __shared__ float sred[256];
    __shared__ float swp[8];               // per-warp partials
    __shared__ float s_pref[PF_FLOATS];
    __shared__ float sC[64];               // [Cb 32 | Cp 32] for the match warp
    __shared__ bool  isLast;

    const bool isMatch = (bid < BT) && (w == 7);

    if (!isMatch) {
        // ------------- Heat warps: strided warp-iterations ----------------
        int h = (bid < BT) ? (bid * 7 + w)
                           : (3584 + (bid - BT) * 8 + w);

        float acc = 0.f;
        for (int it = h; it < NIT; it += NHW) {
            int i = it * 32 + lane;
            float4 x = ha[i];
            float4 y = hb[i];
            float dx = x.x - y.x, dy = x.y - y.y, dz = x.z - y.z, dw = x.w - y.w;
            acc += dx * dx + dy * dy + dz * dz + dw * dw;
        }
#pragma unroll
        for (int o = 16; o > 0; o >>= 1)
            acc += __shfl_down_sync(0xffffffffu, acc, o);
        if (lane == 0) swp[w] = acc;
    } else {
        // ---------------- Match warp (warp 7 of blocks 0..511) ------------
        const int bt = bid;

        // Stage the whole 2.4KB working set as float4 (coalesced, 5/lane).
        for (int c = lane; c < PF_CHUNKS; c += 32) {
            const float* src;
            if      (c <  84) src = pp_all + bt * 336 + c * 4;
            else if (c < 126) src = gp_all + bt * 168 + (c -  84) * 4;
            else if (c < 130) src = pc_all + bt * 16  + (c - 126) * 4;
            else if (c < 132) src = gc_all + bt * 8   + (c - 130) * 4;
            else if (c < 134) src = sc_all + bt * 8   + (c - 132) * 4;
            else if (c < 138) src = po_all + bt * 16  + (c - 134) * 4;
            else if (c < 140) src = go_all + bt * 8   + (c - 138) * 4;
            else if (c < 148) src = ps_all + bt * 32  + (c - 140) * 4;
            else              src = gs_all + bt * 16  + (c - 148) * 4;
            float4 v = *(const float4*)src;
            *(float4*)(s_pref + c * 4) = v;
        }
        __syncwarp();

        const float* s_pp = s_pref + PF_PP;
        const float* s_gp = s_pref + PF_GP;

        // Cost entries: lane = i*4+j covers all 32 (i,j) pairs, from shared.
        const int i = lane >> 2, j = lane & 3;
        {
            float dx = s_pref[PF_PC + 2 * i]     - s_pref[PF_GC + 2 * j];
            float dy = s_pref[PF_PC + 2 * i + 1] - s_pref[PF_GC + 2 * j + 1];
            sC[lane] = sqrtf(dx * dx + dy * dy) - s_pref[PF_SC + i];

            const float* pi = s_pp + i * 42;
            const float* gj = s_gp + j * 42;
            float s = 0.f;
#pragma unroll
            for (int k = 0; k < 42; k++) {
                float d = pi[k] - gj[k];
                s += d * d;
            }
            sC[32 + lane] = sqrtf(s);
        }
        __syncwarp();

        // Sweep all 1680 combos: 56 (d0,d1)-prefixes x 30 each.
        // rank = ((d0*7+d1)*6+d2)*5+d3 (itertools lexicographic order);
        // min over (orderedFloat<<32 | rank) = exact first-argmin.
        unsigned long long kb = ~0ull, kp = ~0ull;
        for (int p = lane; p < 56; p += 32) {
            int d0 = p / 7, d1 = p - d0 * 7;
            int i0 = d0;
            int i1 = d1 + (d1 >= d0);
            int a1 = min(i0, i1), b1 = max(i0, i1);
            float sb01 = sC[i0 * 4 + 0] + sC[i1 * 4 + 1];
            float sp01 = sC[32 + i0 * 4 + 0] + sC[32 + i1 * 4 + 1];
            int rbase = p * 30;
#pragma unroll
            for (int d2 = 0; d2 < 6; d2++) {
                int i2 = d2;
                i2 += (i2 >= a1);
                i2 += (i2 >= b1);
                float sb2 = sb01 + sC[i2 * 4 + 2];
                float sp2 = sp01 + sC[32 + i2 * 4 + 2];
                int a2, b2, c2;
                if (i2 < a1)      { a2 = i2; b2 = a1; c2 = b1; }
                else if (i2 < b1) { a2 = a1; b2 = i2; c2 = b1; }
                else              { a2 = a1; b2 = b1; c2 = i2; }
#pragma unroll
                for (int d3 = 0; d3 < 5; d3++) {
                    int i3 = d3;
                    i3 += (i3 >= a2);
                    i3 += (i3 >= b2);
                    i3 += (i3 >= c2);
                    float tb = sb2 + sC[i3 * 4 + 3];
                    float tp = sp2 + sC[32 + i3 * 4 + 3];
                    unsigned r = (unsigned)(rbase + d2 * 5 + d3);
                    kb = umin64(kb, ((unsigned long long)f2ord(tb) << 32) | r);
                    kp = umin64(kp, ((unsigned long long)f2ord(tp) << 32) | r);
                }
            }
        }
#pragma unroll
        for (int o = 16; o > 0; o >>= 1) {
            kb = umin64(kb, __shfl_xor_sync(0xffffffffu, kb, o));
            kp = umin64(kp, __shfl_xor_sync(0xffffffffu, kp, o));
        }

        int pb[4], pq[4];
        decode_perm((int)(kb & 0xFFFFFFFFu), pb);
        decode_perm((int)(kp & 0xFFFFFFFFu), pq);

        // Tail losses: lane-parallel, all from shared, fixed-order sum.
        float pose_acc = 0.f, box_acc = 0.f;
        for (int idx = lane; idx < 168; idx += 32) {
            int jj = idx / 42, k = idx - jj * 42;
            float d = s_pp[pq[jj] * 42 + k] - s_gp[idx];
            pose_acc += d * d;
        }
        if (lane < 24) {
            int jj = lane / 6, ww = lane - jj * 6;
            int ii = pb[jj];
            if (ww < 2) {
                box_acc = 0.5f * fabsf(s_pref[PF_PO + ii * 2 + ww] -
                                       s_pref[PF_GO + jj * 2 + ww]);
            } else {
                int k = ww - 2;
                box_acc = 0.25f * fabsf(s_pref[PF_PS + ii * 4 + k] -
                                        s_pref[PF_GS + jj * 4 + k]);
            }
        }
        float v = pose_acc * INV_POSE + box_acc * INV_BT;
#pragma unroll
        for (int o = 16; o > 0; o >>= 1)
            v += __shfl_down_sync(0xffffffffu, v, o);
        if (lane == 0) {
            g_match[bt] = v;
            swp[7] = 0.f;            // match warp's heat contribution
        }
    }

    // ---------------- Block reduction over 8 warp partials ----------------
    __syncthreads();
    if (t == 0) {
        float s = ((swp[0] + swp[1]) + (swp[2] + swp[3])) +
                  ((swp[4] + swp[5]) + (swp[6] + swp[7]));
        g_heat_part[bid] = s;
    }

    // ---------------- Last-block ticket combine (threadFenceReduction) ----
    if (t == 0) {
        __threadfence();
        unsigned old = atomicAdd(&g_count, 1u);
        isLast = (old == NBLK - 1);
    }
    __syncthreads();

    if (isLast) {
        __threadfence();
        float v = g_heat_part[t] + g_heat_part[t + 256] +
                  g_heat_part[t + 512] + g_heat_part[t + 768];
        v *= INV_HEAT;
        v += g_match[t] + g_match[t + 256];
        sred[t] = v;
        __syncthreads();
#pragma unroll
        for (int o = 128; o > 0; o >>= 1) {
            if (t < o) sred[t] += sred[t + o];
            __syncthreads();
        }
        if (t == 0) {
            out[0]  = sred[0];
            g_count = 0;             // reset for next graph replay
        }
    }
}

// ---------------------------------------------------------------------------
extern "C" void kernel_launch(void* const* d_in, const int* in_sizes, int n_in,
                              void* d_out, int out_size) {
    const float* hor_heatmap = (const float*)d_in[0];
    const float* hor_offset  = (const float*)d_in[1];
    const float* hor_bsize   = (const float*)d_in[2];
    const float* hor_center  = (const float*)d_in[3];
    const float* scores      = (const float*)d_in[4];
    const float* x_pose3d    = (const float*)d_in[5];
    const float* gt_heatmap  = (const float*)d_in[6];
    const float* gt_boxes_wh = (const float*)d_in[7];
    const float* gt_offset   = (const float*)d_in[8];
    const float* gt_center   = (const float*)d_in[9];
    const float* gt_pose3d   = (const float*)d_in[10];

    k_fused<<<NBLK, 256>>>((const float4*)hor_heatmap, (const float4*)gt_heatmap,
                           hor_offset, hor_bsize, hor_center, scores, x_pose3d,
                           gt_boxes_wh, gt_offset, gt_center, gt_pose3d,
                           (float*)d_out);
}